// round 2
// baseline (speedup 1.0000x reference)
#include <cuda_runtime.h>
#include <cuda_bf16.h>
#include <cstdint>

// Problem constants:
//   x:    (B=64, L=4096) int32 indices into VOCAB
//   w_in: (P=128, VOCAB=32000) float32, row-major
//   out:  (B, P, L) float32, out[b,p,l] = w_in[p, x[b,l]]
#define PB   128
#define VOC  32000
#define BB   64
#define LL   4096

// Transposed weight table w_t[v][p] (16.38 MB, L2-resident).
__device__ float g_wt[(size_t)VOC * PB];

// ---------------------------------------------------------------------------
// Kernel A: transpose w_in(P, VOC) -> g_wt(VOC, P).
// Tile: 32 v  x  128 p, 256 threads.
//   Load : 16 coalesced 128B row reads per thread-group (lanes vary v).
//   STS  : tile[v][p], pitch 129 -> stride-129 across lanes, conflict-free.
//   Read : LDS.128 row reads (lanes stride 4 floats -> all 32 banks).
//   Store: STG.128, 512 B fully-coalesced rows of g_wt.
// ---------------------------------------------------------------------------
#define TP 129   // tile pitch in floats

__global__ __launch_bounds__(256) void transpose_kernel(const float* __restrict__ w_in) {
    __shared__ float tile[32 * TP];
    const int v0   = blockIdx.x * 32;
    const int lane = threadIdx.x & 31;
    const int wrp  = threadIdx.x >> 5;   // 0..7

    // Load 128 p-rows (16 per warp), coalesced along v; conflict-free STS.
    #pragma unroll
    for (int i = 0; i < 16; i++) {
        const int p = wrp + i * 8;
        tile[lane * TP + p] = w_in[(size_t)p * VOC + (v0 + lane)];
    }
    __syncthreads();

    // Write 32 v-rows of g_wt, 512 B each, float4-vectorized.
    #pragma unroll
    for (int i = 0; i < 4; i++) {
        const int vr = wrp + i * 8;
        float4 o;
        o.x = tile[vr * TP + lane * 4 + 0];
        o.y = tile[vr * TP + lane * 4 + 1];
        o.z = tile[vr * TP + lane * 4 + 2];
        o.w = tile[vr * TP + lane * 4 + 3];
        *reinterpret_cast<float4*>(&g_wt[(size_t)(v0 + vr) * PB + lane * 4]) = o;
    }
}

// ---------------------------------------------------------------------------
// Kernel B: smem-free gather.
// Block: 1024 threads = 32 warps; warp w owns p-quad pq = w (p = 4pq..4pq+3).
// Block covers (b = blockIdx.y, tokens l0..l0+127).
// Per warp-iter j: lane i handles token t = l0 + 32j + i:
//   v  = x[b][t]                  (coalesced 128 B, L1-shared across warps)
//   w  = float4 g_wt[v][4pq..+3]  (16 B gather; sector shared with warp pq^1
//                                  in the same block -> L1 absorbs the waste)
//   4x STG.32 rows out[b][4pq+k][t] — 128 B fully coalesced across lanes.
// No shared memory, no barriers.
// ---------------------------------------------------------------------------
#define TC 128   // tokens per block

__global__ __launch_bounds__(1024) void gather_kernel(
    const int* __restrict__ x, float* __restrict__ out) {
    const int lane = threadIdx.x & 31;
    const int pq   = threadIdx.x >> 5;          // 0..31
    const int b    = blockIdx.y;
    const int l0   = blockIdx.x * TC;

    const float4* __restrict__ wt = reinterpret_cast<const float4*>(g_wt); // [VOC][32]
    const int*   xrow = &x[(size_t)b * LL];
    float* __restrict__ obase = &out[((size_t)b * PB + pq * 4) * LL];

    #pragma unroll
    for (int j = 0; j < TC / 32; j++) {
        const int l = l0 + j * 32 + lane;
        const int v = __ldg(&xrow[l]);
        const float4 w = wt[(size_t)v * (PB / 4) + pq];
        obase[l]          = w.x;
        obase[l + LL]     = w.y;
        obase[l + 2 * LL] = w.z;
        obase[l + 3 * LL] = w.w;
    }
}

// ---------------------------------------------------------------------------
// Launch
// ---------------------------------------------------------------------------
extern "C" void kernel_launch(void* const* d_in, const int* in_sizes, int n_in,
                              void* d_out, int out_size) {
    const int*   x    = (const int*)d_in[0];     // (64, 4096) int32
    const float* w_in = (const float*)d_in[1];   // (128, 32000) fp32
    float*       out  = (float*)d_out;           // (64, 128, 4096) fp32

    (void)in_sizes; (void)n_in; (void)out_size;

    transpose_kernel<<<VOC / 32, 256>>>(w_in);
    gather_kernel<<<dim3(LL / TC, BB), 1024>>>(x, out);
}

// round 3
// speedup vs baseline: 1.0335x; 1.0335x over previous
#include <cuda_runtime.h>
#include <cuda_bf16.h>
#include <cstdint>

// out[b,p,l] = w_in[p, x[b,l]];  B=64, L=4096, P=128, VOCAB=32000, fp32.
#define PB   128
#define VOC  32000
#define BB   64
#define LL   4096
#define TOK  64          // tokens per gather block

// Transposed weight table w_t[v][p] (16.38 MB, mostly L2-resident).
__device__ float g_wt[(size_t)VOC * PB];

// ---------------------------------------------------------------------------
// Kernel A: transpose w_in(P, VOC) -> g_wt(VOC, P).
// Tile: 64 v x 128 p per block (32 KB smem), float4 on all paths.
// Phase 1: thread loads 4 p-rows' float4s (along v), 4x4 register transpose,
//          4x STS.128 into v-major swizzled tile (full-bandwidth, 4-phase).
// Phase 2: conflict-free LDS.128 + 512 B coalesced STG.128 rows of g_wt.
// Swizzle: element (v, pc[float4-col]) lives at col' = pc ^ ((v>>2)&7).
// ---------------------------------------------------------------------------
__global__ __launch_bounds__(256) void transpose_kernel(const float* __restrict__ w_in) {
    __shared__ float4 s4[64 * 32];          // rows: v (64), cols: 32 float4 (128 p)
    const int tid = threadIdx.x;
    const int v0  = blockIdx.x * 64;

    const int c = tid & 15;                  // float4-col along v (0..15)
    #pragma unroll
    for (int it = 0; it < 2; it++) {
        const int pg = (tid >> 4) + 16 * it; // p-quad index (0..31)
        float4 a0 = *reinterpret_cast<const float4*>(&w_in[(size_t)(4 * pg + 0) * VOC + v0 + 4 * c]);
        float4 a1 = *reinterpret_cast<const float4*>(&w_in[(size_t)(4 * pg + 1) * VOC + v0 + 4 * c]);
        float4 a2 = *reinterpret_cast<const float4*>(&w_in[(size_t)(4 * pg + 2) * VOC + v0 + 4 * c]);
        float4 a3 = *reinterpret_cast<const float4*>(&w_in[(size_t)(4 * pg + 3) * VOC + v0 + 4 * c]);
        // Register 4x4 transpose: bj = values at v = 4c+j for p = 4pg..4pg+3.
        float4 b0 = make_float4(a0.x, a1.x, a2.x, a3.x);
        float4 b1 = make_float4(a0.y, a1.y, a2.y, a3.y);
        float4 b2 = make_float4(a0.z, a1.z, a2.z, a3.z);
        float4 b3 = make_float4(a0.w, a1.w, a2.w, a3.w);
        const int col = pg ^ (c & 7);        // swizzled p-col; key = (v>>2)&7 = c&7
        s4[(4 * c + 0) * 32 + col] = b0;
        s4[(4 * c + 1) * 32 + col] = b1;
        s4[(4 * c + 2) * 32 + col] = b2;
        s4[(4 * c + 3) * 32 + col] = b3;
    }
    __syncthreads();

    float4* __restrict__ wt4 = reinterpret_cast<float4*>(g_wt);
    #pragma unroll
    for (int k = 0; k < 8; k++) {
        const int idx = tid + 256 * k;       // 2048 = 64 v x 32 pc
        const int v   = idx >> 5;
        const int pc  = idx & 31;
        float4 o = s4[v * 32 + (pc ^ ((v >> 2) & 7))];
        wt4[(size_t)(v0 + v) * 32 + pc] = o;
    }
}

// ---------------------------------------------------------------------------
// Kernel B: gather. Block: 256 threads, (b, 64 tokens). smem tile 32 KB.
// Phase 1: warp w handles token-groups g = {w, w+8} (4 tokens each):
//   4x LDG.128 (512 B coalesced rows of g_wt), 4x4 register transpose,
//   4x STS.128 into p-major swizzled tile s4[p][g ^ ((p>>2)&7)].
// Phase 2: thread (p, tg): conflict-free LDS.128 of tokens 4tg..4tg+3 at p,
//   STG.128 coalesced 256 B runs along l. 8 gmem wavefronts / token total.
// ---------------------------------------------------------------------------
__global__ __launch_bounds__(256) void gather_kernel(
    const int* __restrict__ x, float* __restrict__ out) {
    __shared__ float4 s4[PB * (TOK / 4)];    // rows: p (128), cols: 16 float4 (64 t)
    __shared__ int    sv[TOK];

    const int tid  = threadIdx.x;
    const int lane = tid & 31;
    const int w    = tid >> 5;               // 0..7
    const int b    = blockIdx.y;
    const int l0   = blockIdx.x * TOK;

    if (tid < TOK) sv[tid] = x[(size_t)b * LL + l0 + tid];
    __syncthreads();

    const float4* __restrict__ wt4 = reinterpret_cast<const float4*>(g_wt); // [VOC][32]
    #pragma unroll
    for (int g = w; g < 16; g += 8) {        // token group: tokens 4g..4g+3
        const int t0 = g * 4;
        const int vA = sv[t0 + 0], vB = sv[t0 + 1];
        const int vC = sv[t0 + 2], vD = sv[t0 + 3];
        float4 a0 = wt4[(size_t)vA * 32 + lane];
        float4 a1 = wt4[(size_t)vB * 32 + lane];
        float4 a2 = wt4[(size_t)vC * 32 + lane];
        float4 a3 = wt4[(size_t)vD * 32 + lane];
        // Transpose: bj = tokens {t0..t0+3} at p = 4*lane + j.
        float4 b0 = make_float4(a0.x, a1.x, a2.x, a3.x);
        float4 b1 = make_float4(a0.y, a1.y, a2.y, a3.y);
        float4 b2 = make_float4(a0.z, a1.z, a2.z, a3.z);
        float4 b3 = make_float4(a0.w, a1.w, a2.w, a3.w);
        const int col = g ^ (lane & 7);      // swizzle key = (p>>2)&7 = lane&7
        s4[(4 * lane + 0) * 16 + col] = b0;
        s4[(4 * lane + 1) * 16 + col] = b1;
        s4[(4 * lane + 2) * 16 + col] = b2;
        s4[(4 * lane + 3) * 16 + col] = b3;
    }
    __syncthreads();

    float4* __restrict__ out4 = reinterpret_cast<float4*>(out);
    const size_t obase = ((size_t)b * PB) * (LL / 4) + (l0 >> 2);
    #pragma unroll
    for (int k = 0; k < 8; k++) {
        const int idx = tid + 256 * k;       // 2048 = 128 p x 16 tg
        const int p   = idx >> 4;
        const int tg  = idx & 15;
        float4 o = s4[p * 16 + (tg ^ ((p >> 2) & 7))];
        out4[obase + (size_t)p * (LL / 4) + tg] = o;
    }
}

// ---------------------------------------------------------------------------
// Launch
// ---------------------------------------------------------------------------
extern "C" void kernel_launch(void* const* d_in, const int* in_sizes, int n_in,
                              void* d_out, int out_size) {
    const int*   x    = (const int*)d_in[0];     // (64, 4096) int32
    const float* w_in = (const float*)d_in[1];   // (128, 32000) fp32
    float*       out  = (float*)d_out;           // (64, 128, 4096) fp32
    (void)in_sizes; (void)n_in; (void)out_size;

    transpose_kernel<<<VOC / 64, 256>>>(w_in);
    gather_kernel<<<dim3(LL / TOK, BB), 256>>>(x, out);
}

// round 4
// speedup vs baseline: 1.4632x; 1.4157x over previous
#include <cuda_runtime.h>
#include <cuda_bf16.h>
#include <cstdint>

// out[b,p,l] = w_in[p, x[b,l]];  B=64, L=4096, P=128, VOCAB=32000, fp32.
#define PB   128
#define VOC  32000
#define BB   64
#define LL   4096
#define TOK  64            // tokens per gather block
#define PITCH_B 528        // smem row pitch: 512 B row + 16 B pad = 33 float4 (odd!)
#define PITCH_F4 33

// Transposed weight table w_t[v][p] (16.38 MB, mostly L2-resident).
__device__ __align__(512) float g_wt[(size_t)VOC * PB];

// ---------------- PTX helpers ----------------
__device__ __forceinline__ uint32_t smem_u32(const void* p) {
    return (uint32_t)__cvta_generic_to_shared(p);
}
__device__ __forceinline__ void mbar_init(uint32_t mbar, uint32_t cnt) {
    asm volatile("mbarrier.init.shared.b64 [%0], %1;" :: "r"(mbar), "r"(cnt) : "memory");
}
__device__ __forceinline__ void mbar_expect_tx(uint32_t mbar, uint32_t bytes) {
    asm volatile("mbarrier.arrive.expect_tx.shared.b64 _, [%0], %1;"
                 :: "r"(mbar), "r"(bytes) : "memory");
}
__device__ __forceinline__ void mbar_wait(uint32_t mbar, uint32_t parity) {
    asm volatile(
        "{\n\t"
        ".reg .pred P1;\n\t"
        "WAIT_LOOP_%=:\n\t"
        "mbarrier.try_wait.parity.acquire.cta.shared::cta.b64 P1, [%0], %1, 0x989680;\n\t"
        "@P1 bra.uni WAIT_DONE_%=;\n\t"
        "bra.uni WAIT_LOOP_%=;\n\t"
        "WAIT_DONE_%=:\n\t"
        "}"
        :: "r"(mbar), "r"(parity) : "memory");
}
__device__ __forceinline__ void bulk_g2s(uint32_t dst_smem, const void* src_gmem,
                                         uint32_t bytes, uint32_t mbar) {
    asm volatile(
        "cp.async.bulk.shared::cluster.global.mbarrier::complete_tx::bytes "
        "[%0], [%1], %2, [%3];"
        :: "r"(dst_smem), "l"(src_gmem), "r"(bytes), "r"(mbar) : "memory");
}
__device__ __forceinline__ void bulk_s2g(void* dst_gmem, uint32_t src_smem, uint32_t bytes) {
    asm volatile(
        "cp.async.bulk.global.shared::cta.bulk_group [%0], [%1], %2;"
        :: "l"(dst_gmem), "r"(src_smem), "r"(bytes) : "memory");
}
__device__ __forceinline__ void fence_async_shared() {
    asm volatile("fence.proxy.async.shared::cta;" ::: "memory");
}

// ---------------------------------------------------------------------------
// Kernel A: transpose w_in(P, VOC) -> g_wt(VOC, P).
// Block: 256 threads, tile = 64 v-rows x 128 p (rows padded to 528 B).
// Phase 1: 4 coalesced LDG.32 (p, p+1, p+2, p+3 at same v) -> float4 over p,
//          STS.128 at s4[v*33 + pq]: quad-bank (v+pq)%8 -> conflict-free.
// Phase 2: 64 bulk S2G stores: 512 B smem row -> g_wt[v0+t] (zero LSU legs).
// ---------------------------------------------------------------------------
__global__ __launch_bounds__(256) void transpose_kernel(const float* __restrict__ w_in) {
    __shared__ __align__(16) float tile[64 * (PITCH_B / 4)];
    float4* s4 = reinterpret_cast<float4*>(tile);

    const int tid  = threadIdx.x;
    const int lane = tid & 31;
    const int wrp  = tid >> 5;
    const int v0   = blockIdx.x * 64;

    #pragma unroll
    for (int k = 0; k < 8; k++) {
        const int idx = wrp + 8 * k;        // 0..63
        const int pq  = idx >> 1;           // p-quad 0..31
        const int vh  = idx & 1;
        const int v   = vh * 32 + lane;     // 0..63
        const size_t base = (size_t)(4 * pq) * VOC + v0 + v;
        float4 f;
        f.x = w_in[base];
        f.y = w_in[base + VOC];
        f.z = w_in[base + 2 * (size_t)VOC];
        f.w = w_in[base + 3 * (size_t)VOC];
        s4[v * PITCH_F4 + pq] = f;
    }
    __syncthreads();

    if (tid < 64) {
        fence_async_shared();
        bulk_s2g(&g_wt[(size_t)(v0 + tid) * PB],
                 smem_u32(tile) + tid * PITCH_B, 512);
        asm volatile("cp.async.bulk.commit_group;" ::: "memory");
        asm volatile("cp.async.bulk.wait_group 0;" ::: "memory");
    }
}

// ---------------------------------------------------------------------------
// Kernel B: gather. Block: 256 threads, (b = blockIdx.y, 64 tokens).
// Phase 1: threads 0..63 each issue one 512 B bulk G2S: g_wt[x[b][l0+t]] ->
//          smem row t (pitch 528 B). mbarrier expect_tx = 32 KB. Zero LSU.
// Phase 2: warp-iter (q, h): lane t = 32h+lane reads float4 s4[t*33+q]
//          (conflict-free vertical LDS.128), then 4x STG.32 rows
//          out[b][4q+j][l0+t] — 128 B fully coalesced.
// ---------------------------------------------------------------------------
__global__ __launch_bounds__(256) void gather_kernel(
    const int* __restrict__ x, float* __restrict__ out) {
    __shared__ __align__(16) float tile[TOK * (PITCH_B / 4)];
    __shared__ __align__(8) unsigned long long mbar_storage;
    const float4* s4 = reinterpret_cast<const float4*>(tile);
    const uint32_t mbar = smem_u32(&mbar_storage);

    const int tid  = threadIdx.x;
    const int lane = tid & 31;
    const int wrp  = tid >> 5;
    const int b    = blockIdx.y;
    const int l0   = blockIdx.x * TOK;

    if (tid == 0) mbar_init(mbar, 1);
    __syncthreads();
    if (tid == 0) mbar_expect_tx(mbar, TOK * 512);
    if (tid < TOK) {
        const int v = x[(size_t)b * LL + l0 + tid];
        bulk_g2s(smem_u32(tile) + tid * PITCH_B, &g_wt[(size_t)v * PB], 512, mbar);
    }
    mbar_wait(mbar, 0);

    #pragma unroll
    for (int k = 0; k < 8; k++) {
        const int it = wrp * 8 + k;         // 0..63
        const int q  = it >> 1;             // p-quad 0..31
        const int h  = it & 1;
        const int t  = h * 32 + lane;       // token within tile
        const float4 f = s4[t * PITCH_F4 + q];
        float* __restrict__ orow =
            &out[((size_t)b * PB + 4 * q) * LL + l0 + t];
        orow[0]           = f.x;
        orow[(size_t)LL]      = f.y;
        orow[(size_t)2 * LL]  = f.z;
        orow[(size_t)3 * LL]  = f.w;
    }
}

// ---------------------------------------------------------------------------
// Launch
// ---------------------------------------------------------------------------
extern "C" void kernel_launch(void* const* d_in, const int* in_sizes, int n_in,
                              void* d_out, int out_size) {
    const int*   x    = (const int*)d_in[0];     // (64, 4096) int32
    const float* w_in = (const float*)d_in[1];   // (128, 32000) fp32
    float*       out  = (float*)d_out;           // (64, 128, 4096) fp32
    (void)in_sizes; (void)n_in; (void)out_size;

    transpose_kernel<<<VOC / 64, 256>>>(w_in);
    gather_kernel<<<dim3(LL / TOK, BB), 256>>>(x, out);
}

// round 5
// speedup vs baseline: 1.5063x; 1.0295x over previous
#include <cuda_runtime.h>
#include <cuda_bf16.h>
#include <cstdint>

// out[b,p,l] = w_in[p, x[b,l]];  B=64, L=4096, P=128, VOCAB=32000, fp32.
#define PB   128
#define VOC  32000
#define BB   64
#define LL   4096
#define TOK  64            // tokens per gather block
#define PITCH_B 528        // smem row pitch: 512 B + 16 B pad = 33 float4 (odd)
#define PITCH_F4 33

// Transposed weight table w_t[v][p] (16.38 MB, mostly L2-resident).
__device__ __align__(512) float g_wt[(size_t)VOC * PB];

// ---------------- PTX helpers ----------------
__device__ __forceinline__ uint32_t smem_u32(const void* p) {
    return (uint32_t)__cvta_generic_to_shared(p);
}
__device__ __forceinline__ void mbar_init(uint32_t mbar, uint32_t cnt) {
    asm volatile("mbarrier.init.shared.b64 [%0], %1;" :: "r"(mbar), "r"(cnt) : "memory");
}
__device__ __forceinline__ void mbar_expect_tx(uint32_t mbar, uint32_t bytes) {
    asm volatile("mbarrier.arrive.expect_tx.shared.b64 _, [%0], %1;"
                 :: "r"(mbar), "r"(bytes) : "memory");
}
__device__ __forceinline__ void mbar_wait(uint32_t mbar, uint32_t parity) {
    asm volatile(
        "{\n\t"
        ".reg .pred P1;\n\t"
        "WAIT_LOOP_%=:\n\t"
        "mbarrier.try_wait.parity.acquire.cta.shared::cta.b64 P1, [%0], %1, 0x989680;\n\t"
        "@P1 bra.uni WAIT_DONE_%=;\n\t"
        "bra.uni WAIT_LOOP_%=;\n\t"
        "WAIT_DONE_%=:\n\t"
        "}"
        :: "r"(mbar), "r"(parity) : "memory");
}
__device__ __forceinline__ void bulk_g2s(uint32_t dst_smem, const void* src_gmem,
                                         uint32_t bytes, uint32_t mbar) {
    asm volatile(
        "cp.async.bulk.shared::cluster.global.mbarrier::complete_tx::bytes "
        "[%0], [%1], %2, [%3];"
        :: "r"(dst_smem), "l"(src_gmem), "r"(bytes), "r"(mbar) : "memory");
}
__device__ __forceinline__ void bulk_s2g(void* dst_gmem, uint32_t src_smem, uint32_t bytes) {
    asm volatile(
        "cp.async.bulk.global.shared::cta.bulk_group [%0], [%1], %2;"
        :: "l"(dst_gmem), "r"(src_smem), "r"(bytes) : "memory");
}
__device__ __forceinline__ void fence_async_shared() {
    asm volatile("fence.proxy.async.shared::cta;" ::: "memory");
}

// ---------------------------------------------------------------------------
// Kernel A: transpose w_in(P, VOC) -> g_wt(VOC, P).
// 1000 blocks (32 v x 128 p tiles, 16.9 KB smem -> high occupancy).
// Phase 1: warp w, iter i: q = 4w+i; lane v = lane. 4 coalesced LDG.32
//   (p = 4q..4q+3 at v) -> STS.128 s4[lane*33+q], bank (lane+q)%8 distinct
//   per 8-lane phase -> conflict-free.
// Phase 2: 32 bulk S2G: 512 B smem row -> g_wt[v0+v]. Zero LSU store legs.
// ---------------------------------------------------------------------------
__global__ __launch_bounds__(256) void transpose_kernel(const float* __restrict__ w_in) {
    __shared__ __align__(16) float tile[32 * PITCH_F4 * 4];
    float4* s4 = reinterpret_cast<float4*>(tile);

    const int tid  = threadIdx.x;
    const int lane = tid & 31;
    const int wrp  = tid >> 5;
    const int v0   = blockIdx.x * 32;

    #pragma unroll
    for (int i = 0; i < 4; i++) {
        const int q = wrp * 4 + i;               // p-quad 0..31
        const size_t base = (size_t)(4 * q) * VOC + v0 + lane;
        float4 f;
        f.x = w_in[base];
        f.y = w_in[base + (size_t)VOC];
        f.z = w_in[base + 2 * (size_t)VOC];
        f.w = w_in[base + 3 * (size_t)VOC];
        s4[lane * PITCH_F4 + q] = f;
    }
    __syncthreads();

    if (tid < 32) {
        fence_async_shared();
        bulk_s2g(&g_wt[(size_t)(v0 + tid) * PB],
                 smem_u32(tile) + tid * PITCH_B, 512);
        asm volatile("cp.async.bulk.commit_group;" ::: "memory");
        asm volatile("cp.async.bulk.wait_group 0;" ::: "memory");
    }
}

// ---------------------------------------------------------------------------
// Kernel B: gather. Block: 256 threads, (b = blockIdx.y, 64 tokens).
// Token t's 512 B row lands at smem row R(t) = (t&3)*16 + (t>>2).
// Two mbarriers split the tile into halves by g = t>>2 (g<8 vs g>=8); all 64
// TMA fetches are issued up front, phase 2 of half 0 overlaps half 1's DMA.
// Phase 2 (per half h): thread (g = h*8 + (lane&7), q = 4*wrp + (lane>>3)):
//   4x LDS.128 rows 16j+g (bank (g+q)%8 -> conflict-free), 4x4 register
//   transpose, 4x STG.128 out[b][4q+j][l0+4g] — 4x128 B coalesced segments.
// ---------------------------------------------------------------------------
__global__ __launch_bounds__(256) void gather_kernel(
    const int* __restrict__ x, float* __restrict__ out) {
    __shared__ __align__(16) float tile[TOK * PITCH_F4 * 4];
    __shared__ __align__(8) unsigned long long mbar_storage[2];
    const float4* s4 = reinterpret_cast<const float4*>(tile);
    const uint32_t mbar0 = smem_u32(&mbar_storage[0]);
    const uint32_t mbar1 = smem_u32(&mbar_storage[1]);

    const int tid  = threadIdx.x;
    const int lane = tid & 31;
    const int wrp  = tid >> 5;
    const int b    = blockIdx.y;
    const int l0   = blockIdx.x * TOK;

    if (tid == 0) { mbar_init(mbar0, 1); mbar_init(mbar1, 1); }
    __syncthreads();
    if (tid == 0) {
        mbar_expect_tx(mbar0, 32 * 512);
        mbar_expect_tx(mbar1, 32 * 512);
    }
    if (tid < TOK) {
        const int v = x[(size_t)b * LL + l0 + tid];
        const int R = (tid & 3) * 16 + (tid >> 2);
        bulk_g2s(smem_u32(tile) + R * PITCH_B, &g_wt[(size_t)v * PB], 512,
                 (tid >> 2) < 8 ? mbar0 : mbar1);
    }

    const int g0 = lane & 7;
    const int q  = wrp * 4 + (lane >> 3);        // p-quad 0..31

    #pragma unroll
    for (int h = 0; h < 2; h++) {
        mbar_wait(h == 0 ? mbar0 : mbar1, 0);
        const int g = h * 8 + g0;                // token group: tokens 4g..4g+3
        // Row 16j+g holds token 4g+j; f4 col q = p-quad (4q..4q+3).
        float4 f0 = s4[(16 * 0 + g) * PITCH_F4 + q];
        float4 f1 = s4[(16 * 1 + g) * PITCH_F4 + q];
        float4 f2 = s4[(16 * 2 + g) * PITCH_F4 + q];
        float4 f3 = s4[(16 * 3 + g) * PITCH_F4 + q];
        // Transpose: oj = tokens {4g..4g+3} at p = 4q+j.
        float4 o0 = make_float4(f0.x, f1.x, f2.x, f3.x);
        float4 o1 = make_float4(f0.y, f1.y, f2.y, f3.y);
        float4 o2 = make_float4(f0.z, f1.z, f2.z, f3.z);
        float4 o3 = make_float4(f0.w, f1.w, f2.w, f3.w);
        float4* __restrict__ obase = reinterpret_cast<float4*>(
            &out[((size_t)b * PB + 4 * q) * LL + l0 + 4 * g]);
        const size_t rstride = LL / 4;           // float4s per p-row
        obase[0]           = o0;
        obase[rstride]     = o1;
        obase[2 * rstride] = o2;
        obase[3 * rstride] = o3;
    }
}

// ---------------------------------------------------------------------------
// Launch
// ---------------------------------------------------------------------------
extern "C" void kernel_launch(void* const* d_in, const int* in_sizes, int n_in,
                              void* d_out, int out_size) {
    const int*   x    = (const int*)d_in[0];     // (64, 4096) int32
    const float* w_in = (const float*)d_in[1];   // (128, 32000) fp32
    float*       out  = (float*)d_out;           // (64, 128, 4096) fp32
    (void)in_sizes; (void)n_in; (void)out_size;

    transpose_kernel<<<VOC / 32, 256>>>(w_in);
    gather_kernel<<<dim3(LL / TOK, BB), 256>>>(x, out);
}

// round 6
// speedup vs baseline: 1.5467x; 1.0268x over previous
#include <cuda_runtime.h>
#include <cuda_bf16.h>
#include <cstdint>

// out[b,p,l] = w_in[p, x[b,l]];  B=64, L=4096, P=128, VOCAB=32000, fp32.
#define PB   128
#define VOC  32000
#define BB   64
#define LL   4096
#define TOK  32            // tokens per gather block
#define PITCH_B 528        // smem row pitch: 512 B + 16 B pad = 33 float4 (odd)
#define PITCH_F4 33

// Transposed weight table w_t[v][p] (16.38 MB, mostly L2-resident).
__device__ __align__(512) float g_wt[(size_t)VOC * PB];

// ---------------- PTX helpers ----------------
__device__ __forceinline__ uint32_t smem_u32(const void* p) {
    return (uint32_t)__cvta_generic_to_shared(p);
}
__device__ __forceinline__ void mbar_init(uint32_t mbar, uint32_t cnt) {
    asm volatile("mbarrier.init.shared.b64 [%0], %1;" :: "r"(mbar), "r"(cnt) : "memory");
}
__device__ __forceinline__ void mbar_expect_tx(uint32_t mbar, uint32_t bytes) {
    asm volatile("mbarrier.arrive.expect_tx.shared.b64 _, [%0], %1;"
                 :: "r"(mbar), "r"(bytes) : "memory");
}
__device__ __forceinline__ void mbar_wait(uint32_t mbar, uint32_t parity) {
    asm volatile(
        "{\n\t"
        ".reg .pred P1;\n\t"
        "WAIT_LOOP_%=:\n\t"
        "mbarrier.try_wait.parity.acquire.cta.shared::cta.b64 P1, [%0], %1, 0x989680;\n\t"
        "@P1 bra.uni WAIT_DONE_%=;\n\t"
        "bra.uni WAIT_LOOP_%=;\n\t"
        "WAIT_DONE_%=:\n\t"
        "}"
        :: "r"(mbar), "r"(parity) : "memory");
}
__device__ __forceinline__ void bulk_g2s(uint32_t dst_smem, const void* src_gmem,
                                         uint32_t bytes, uint32_t mbar) {
    asm volatile(
        "cp.async.bulk.shared::cluster.global.mbarrier::complete_tx::bytes "
        "[%0], [%1], %2, [%3];"
        :: "r"(dst_smem), "l"(src_gmem), "r"(bytes), "r"(mbar) : "memory");
}

// ---------------------------------------------------------------------------
// Kernel A: transpose w_in(P, VOC) -> g_wt(VOC, P).
// 1000 blocks, tile = 32 v x 128 p (16.9 KB smem), 256 threads, 8 blocks/SM.
// Phase 1: warp w, iter i: q = 4w+i. 4 coalesced 128 B LDG.32 (p=4q..4q+3,
//   lanes vary v) -> STS.128 s4[lane*33+q]: bank (lane+q)%8 conflict-free.
// Phase 2: iter i: v = 4*wrp+i. LDS.128 s4[v*33+lane] ((v+lane)%8 -> CF),
//   STG.128 to g_wt[v0+v][4*lane] — 512 B fully-coalesced rows.
// ---------------------------------------------------------------------------
__global__ __launch_bounds__(256) void transpose_kernel(const float* __restrict__ w_in) {
    __shared__ __align__(16) float tile[32 * PITCH_F4 * 4];
    float4* s4 = reinterpret_cast<float4*>(tile);

    const int tid  = threadIdx.x;
    const int lane = tid & 31;
    const int wrp  = tid >> 5;
    const int v0   = blockIdx.x * 32;

    #pragma unroll
    for (int i = 0; i < 4; i++) {
        const int q = wrp * 4 + i;               // p-quad 0..31
        const size_t base = (size_t)(4 * q) * VOC + v0 + lane;
        float4 f;
        f.x = w_in[base];
        f.y = w_in[base + (size_t)VOC];
        f.z = w_in[base + 2 * (size_t)VOC];
        f.w = w_in[base + 3 * (size_t)VOC];
        s4[lane * PITCH_F4 + q] = f;
    }
    __syncthreads();

    float4* __restrict__ wt4 = reinterpret_cast<float4*>(g_wt);
    #pragma unroll
    for (int i = 0; i < 4; i++) {
        const int v = wrp * 4 + i;               // v-row 0..31
        const float4 f = s4[v * PITCH_F4 + lane];
        wt4[(size_t)(v0 + v) * 32 + lane] = f;
    }
}

// ---------------------------------------------------------------------------
// Kernel B: gather. Block: 128 threads, (b = blockIdx.y, 32 tokens).
// smem: 32 rows x 528 B = 16.9 KB -> ~13 resident blocks/SM.
// Token t (g=t>>2, j=t&3) lands at row R = 2g + (j&1) + 16*(j>>1)
//   (bijection; makes phase-2 LDS banks (2g+q+const)%8 -> conflict-free).
// Two mbarriers: tokens 0..15 / 16..31 (8 KB halves), all TMA up front.
// Phase 2 half h: thread (g = 4h + (lane&3), q = wrp*8 + (lane>>2)):
//   4x LDS.128 (rows R(g,j), col q), 4x4 register transpose, 4x STG.128 —
//   lanes 0-3 write 64 B-contiguous f4 runs along l (full sectors).
// ---------------------------------------------------------------------------
__global__ __launch_bounds__(128) void gather_kernel(
    const int* __restrict__ x, float* __restrict__ out) {
    __shared__ __align__(16) float tile[TOK * PITCH_F4 * 4];
    __shared__ __align__(8) unsigned long long mbar_storage[2];
    const float4* s4 = reinterpret_cast<const float4*>(tile);
    const uint32_t mbar0 = smem_u32(&mbar_storage[0]);
    const uint32_t mbar1 = smem_u32(&mbar_storage[1]);

    const int tid  = threadIdx.x;
    const int lane = tid & 31;
    const int wrp  = tid >> 5;
    const int b    = blockIdx.y;
    const int l0   = blockIdx.x * TOK;

    if (tid == 0) { mbar_init(mbar0, 1); mbar_init(mbar1, 1); }
    __syncthreads();
    if (tid == 0) {
        mbar_expect_tx(mbar0, 16 * 512);
        mbar_expect_tx(mbar1, 16 * 512);
    }
    if (tid < TOK) {
        const int v = x[(size_t)b * LL + l0 + tid];
        const int g = tid >> 2, j = tid & 3;
        const int R = 2 * g + (j & 1) + 16 * (j >> 1);
        bulk_g2s(smem_u32(tile) + R * PITCH_B, &g_wt[(size_t)v * PB], 512,
                 tid < 16 ? mbar0 : mbar1);
    }

    const int gl = lane & 3;                     // token-group within half
    const int q  = wrp * 8 + (lane >> 2);        // p-quad 0..31
    float4* __restrict__ out4 = reinterpret_cast<float4*>(out);
    const size_t rstride = LL / 4;               // float4s per p-row

    #pragma unroll
    for (int h = 0; h < 2; h++) {
        mbar_wait(h == 0 ? mbar0 : mbar1, 0);
        const int g = h * 4 + gl;                // token group (tokens 4g..4g+3)
        // Rows R(g,j) = 2g + (j&1) + 16*(j>>1).
        const int r0 = 2 * g;
        float4 f0 = s4[(r0 + 0)  * PITCH_F4 + q];   // j=0
        float4 f1 = s4[(r0 + 1)  * PITCH_F4 + q];   // j=1
        float4 f2 = s4[(r0 + 16) * PITCH_F4 + q];   // j=2
        float4 f3 = s4[(r0 + 17) * PITCH_F4 + q];   // j=3
        // Transpose: oj = tokens {4g..4g+3} at p = 4q+j.
        float4 o0 = make_float4(f0.x, f1.x, f2.x, f3.x);
        float4 o1 = make_float4(f0.y, f1.y, f2.y, f3.y);
        float4 o2 = make_float4(f0.z, f1.z, f2.z, f3.z);
        float4 o3 = make_float4(f0.w, f1.w, f2.w, f3.w);
        const size_t obase = ((size_t)b * PB + 4 * q) * rstride + (l0 >> 2) + g;
        out4[obase]               = o0;
        out4[obase + rstride]     = o1;
        out4[obase + 2 * rstride] = o2;
        out4[obase + 3 * rstride] = o3;
    }
}

// ---------------------------------------------------------------------------
// Launch
// ---------------------------------------------------------------------------
extern "C" void kernel_launch(void* const* d_in, const int* in_sizes, int n_in,
                              void* d_out, int out_size) {
    const int*   x    = (const int*)d_in[0];     // (64, 4096) int32
    const float* w_in = (const float*)d_in[1];   // (128, 32000) fp32
    float*       out  = (float*)d_out;           // (64, 128, 4096) fp32
    (void)in_sizes; (void)n_in; (void)out_size;

    transpose_kernel<<<VOC / 32, 256>>>(w_in);
    gather_kernel<<<dim3(LL / TOK, BB), 128>>>(x, out);
}

// round 7
// speedup vs baseline: 1.7209x; 1.1126x over previous
#include <cuda_runtime.h>
#include <cuda_bf16.h>
#include <cstdint>

// out[b,p,l] = w_in[p, x[b,l]];  B=64, L=4096, P=128, VOCAB=32000, fp32.
#define PB   128
#define VOC  32000
#define BB   64
#define LL   4096
#define TOK  32            // tokens per gather block
#define PITCH_B 528        // smem row pitch: 512 B + 16 B pad = 33 float4 (odd)
#define PITCH_F4 33

// Transposed weight table w_t[v][p] (16.38 MB, mostly L2-resident).
__device__ __align__(512) float g_wt[(size_t)VOC * PB];

// ---------------- PTX helpers ----------------
__device__ __forceinline__ uint32_t smem_u32(const void* p) {
    return (uint32_t)__cvta_generic_to_shared(p);
}
__device__ __forceinline__ void mbar_init(uint32_t mbar, uint32_t cnt) {
    asm volatile("mbarrier.init.shared.b64 [%0], %1;" :: "r"(mbar), "r"(cnt) : "memory");
}
__device__ __forceinline__ void mbar_expect_tx(uint32_t mbar, uint32_t bytes) {
    asm volatile("mbarrier.arrive.expect_tx.shared.b64 _, [%0], %1;"
                 :: "r"(mbar), "r"(bytes) : "memory");
}
__device__ __forceinline__ void mbar_wait(uint32_t mbar, uint32_t parity) {
    asm volatile(
        "{\n\t"
        ".reg .pred P1;\n\t"
        "WAIT_LOOP_%=:\n\t"
        "mbarrier.try_wait.parity.acquire.cta.shared::cta.b64 P1, [%0], %1, 0x989680;\n\t"
        "@P1 bra.uni WAIT_DONE_%=;\n\t"
        "bra.uni WAIT_LOOP_%=;\n\t"
        "WAIT_DONE_%=:\n\t"
        "}"
        :: "r"(mbar), "r"(parity) : "memory");
}
__device__ __forceinline__ void bulk_g2s(uint32_t dst_smem, const void* src_gmem,
                                         uint32_t bytes, uint32_t mbar) {
    asm volatile(
        "cp.async.bulk.shared::cluster.global.mbarrier::complete_tx::bytes "
        "[%0], [%1], %2, [%3];"
        :: "r"(dst_smem), "l"(src_gmem), "r"(bytes), "r"(mbar) : "memory");
}

// ---------------------------------------------------------------------------
// Kernel A: transpose w_in(P, VOC) -> g_wt(VOC, P).  Zero smem, zero sync.
// Grid (250, 4): block covers 128 v x 32 p. Warp w owns p-quad p0 = by*32+4w;
// lane owns v-quad v0 + 4*lane.
//   Reads : 4x LDG.128, each 512 B fully-coalesced along v.
//   Writes: 4x STG.128, 16 B per lane at stride 512 B (scattered); the other
//           half of each 32 B sector is written by a neighbor warp in the
//           same residency window -> L2 dirty-merge absorbs the waste.
// 8 mem instrs / thread, full occupancy, deep MLP.
// ---------------------------------------------------------------------------
__global__ __launch_bounds__(256) void transpose_kernel(const float* __restrict__ w_in) {
    const int lane = threadIdx.x & 31;
    const int wrp  = threadIdx.x >> 5;           // 0..7
    const int v0   = blockIdx.x * 128;
    const int p0   = blockIdx.y * 32 + 4 * wrp;
    const int v    = v0 + 4 * lane;

    const size_t base = (size_t)p0 * VOC + v;
    const float4 a0 = *reinterpret_cast<const float4*>(&w_in[base]);
    const float4 a1 = *reinterpret_cast<const float4*>(&w_in[base + (size_t)VOC]);
    const float4 a2 = *reinterpret_cast<const float4*>(&w_in[base + 2 * (size_t)VOC]);
    const float4 a3 = *reinterpret_cast<const float4*>(&w_in[base + 3 * (size_t)VOC]);

    float4* __restrict__ dst = reinterpret_cast<float4*>(&g_wt[(size_t)v * PB + p0]);
    const size_t rs = PB / 4;                    // f4 stride between v-rows
    dst[0]      = make_float4(a0.x, a1.x, a2.x, a3.x);   // v
    dst[rs]     = make_float4(a0.y, a1.y, a2.y, a3.y);   // v+1
    dst[2 * rs] = make_float4(a0.z, a1.z, a2.z, a3.z);   // v+2
    dst[3 * rs] = make_float4(a0.w, a1.w, a2.w, a3.w);   // v+3
}

// ---------------------------------------------------------------------------
// Kernel B: gather. Block: 128 threads, (b = blockIdx.y, 32 tokens).
// Token t (g=t>>2, j=t&3) lands at smem row R = 2g + (j&1) + 16*(j>>1).
// Two mbarriers (tokens 0..15 / 16..31, 8 KB halves), all TMA up front.
// Phase 2 half h: thread (g = 4h + (lane&3), q = wrp*8 + (lane>>2)):
//   4x conflict-free LDS.128, 4x4 register transpose, 4x STG.128 (__stcs:
//   streaming writes don't evict the L2-resident g_wt table).
// ---------------------------------------------------------------------------
__global__ __launch_bounds__(128) void gather_kernel(
    const int* __restrict__ x, float* __restrict__ out) {
    __shared__ __align__(16) float tile[TOK * PITCH_F4 * 4];
    __shared__ __align__(8) unsigned long long mbar_storage[2];
    const float4* s4 = reinterpret_cast<const float4*>(tile);
    const uint32_t mbar0 = smem_u32(&mbar_storage[0]);
    const uint32_t mbar1 = smem_u32(&mbar_storage[1]);

    const int tid  = threadIdx.x;
    const int lane = tid & 31;
    const int wrp  = tid >> 5;
    const int b    = blockIdx.y;
    const int l0   = blockIdx.x * TOK;

    if (tid == 0) { mbar_init(mbar0, 1); mbar_init(mbar1, 1); }
    __syncthreads();
    if (tid == 0) {
        mbar_expect_tx(mbar0, 16 * 512);
        mbar_expect_tx(mbar1, 16 * 512);
    }
    if (tid < TOK) {
        const int v = x[(size_t)b * LL + l0 + tid];
        const int g = tid >> 2, j = tid & 3;
        const int R = 2 * g + (j & 1) + 16 * (j >> 1);
        bulk_g2s(smem_u32(tile) + R * PITCH_B, &g_wt[(size_t)v * PB], 512,
                 tid < 16 ? mbar0 : mbar1);
    }

    const int gl = lane & 3;                     // token-group within half
    const int q  = wrp * 8 + (lane >> 2);        // p-quad 0..31
    float4* __restrict__ out4 = reinterpret_cast<float4*>(out);
    const size_t rstride = LL / 4;               // float4s per p-row

    #pragma unroll
    for (int h = 0; h < 2; h++) {
        mbar_wait(h == 0 ? mbar0 : mbar1, 0);
        const int g = h * 4 + gl;                // token group (tokens 4g..4g+3)
        const int r0 = 2 * g;
        float4 f0 = s4[(r0 + 0)  * PITCH_F4 + q];   // j=0
        float4 f1 = s4[(r0 + 1)  * PITCH_F4 + q];   // j=1
        float4 f2 = s4[(r0 + 16) * PITCH_F4 + q];   // j=2
        float4 f3 = s4[(r0 + 17) * PITCH_F4 + q];   // j=3
        // Transpose: oj = tokens {4g..4g+3} at p = 4q+j.
        float4 o0 = make_float4(f0.x, f1.x, f2.x, f3.x);
        float4 o1 = make_float4(f0.y, f1.y, f2.y, f3.y);
        float4 o2 = make_float4(f0.z, f1.z, f2.z, f3.z);
        float4 o3 = make_float4(f0.w, f1.w, f2.w, f3.w);
        const size_t obase = ((size_t)b * PB + 4 * q) * rstride + (l0 >> 2) + g;
        __stcs(&out4[obase],               o0);
        __stcs(&out4[obase + rstride],     o1);
        __stcs(&out4[obase + 2 * rstride], o2);
        __stcs(&out4[obase + 3 * rstride], o3);
    }
}

// ---------------------------------------------------------------------------
// Launch
// ---------------------------------------------------------------------------
extern "C" void kernel_launch(void* const* d_in, const int* in_sizes, int n_in,
                              void* d_out, int out_size) {
    const int*   x    = (const int*)d_in[0];     // (64, 4096) int32
    const float* w_in = (const float*)d_in[1];   // (128, 32000) fp32
    float*       out  = (float*)d_out;           // (64, 128, 4096) fp32
    (void)in_sizes; (void)n_in; (void)out_size;

    transpose_kernel<<<dim3(VOC / 128, 4), 256>>>(w_in);
    gather_kernel<<<dim3(LL / TOK, BB), 128>>>(x, out);
}